// round 2
// baseline (speedup 1.0000x reference)
#include <cuda_runtime.h>
#include <math.h>

#define BS    64
#define NC    80
#define NA    8400
#define TOPK  13
#define EPSF  1e-9f
#define NTHR  256

// Scratch: norm_align_metric accumulated via atomicMax on float bits (all values >= 0).
__device__ unsigned int d_norm_bits[NA];

__global__ void taa_zero_norm() {
    int i = blockIdx.x * blockDim.x + threadIdx.x;
    if (i < NA) d_norm_bits[i] = 0u;
}

// One block per batch row. Computes align metric for all anchors, extracts
// top-13 (tie-break: lower index first, matching jax.lax.top_k stability),
// writes mask_pos row, and scatters norm contributions.
__global__ __launch_bounds__(NTHR) void taa_assign(
    const float* __restrict__ pd_scores,   // (BS, NC, NA)
    const float* __restrict__ pd_bboxes,   // (BS, 4, NA)
    const int*   __restrict__ gt_labels,   // (BS,)
    const float* __restrict__ gt_bboxes,   // (BS, 4)
    float*       __restrict__ mask_out)    // (BS, NA)
{
    __shared__ float s_align[NA];
    __shared__ float s_redv[NTHR];
    __shared__ int   s_redi[NTHR];
    __shared__ float s_topv[TOPK];
    __shared__ int   s_topi[TOPK];
    __shared__ float s_iou[TOPK];
    __shared__ float s_ratio;

    const int b   = blockIdx.x;
    const int tid = threadIdx.x;

    const float gx1 = gt_bboxes[b * 4 + 0];
    const float gy1 = gt_bboxes[b * 4 + 1];
    const float gx2 = gt_bboxes[b * 4 + 2];
    const float gy2 = gt_bboxes[b * 4 + 3];
    const float area1 = fmaxf(gx2 - gx1, 0.f) * fmaxf(gy2 - gy1, 0.f);
    const int   label = gt_labels[b];

    const float* __restrict__ px1 = pd_bboxes + ((long)b * 4 + 0) * NA;
    const float* __restrict__ py1 = pd_bboxes + ((long)b * 4 + 1) * NA;
    const float* __restrict__ px2 = pd_bboxes + ((long)b * 4 + 2) * NA;
    const float* __restrict__ py2 = pd_bboxes + ((long)b * 4 + 3) * NA;
    const float* __restrict__ sc  = pd_scores + ((long)b * NC + label) * NA;
    float* __restrict__ mrow = mask_out + (long)b * NA;

    // Pass 1: align metric into smem; zero the mask row.
    for (int a = tid; a < NA; a += NTHR) {
        float bx1 = px1[a], by1 = py1[a], bx2 = px2[a], by2 = py2[a];
        float iw = fmaxf(fminf(gx2, bx2) - fmaxf(gx1, bx1), 0.f);
        float ih = fmaxf(fminf(gy2, by2) - fmaxf(gy1, by1), 0.f);
        float ov = iw * ih;
        float a2 = fmaxf(bx2 - bx1, 0.f) * fmaxf(by2 - by1, 0.f);
        float iou = ov / (area1 + a2 - ov + EPSF);
        s_align[a] = sc[a] * powf(iou, 6.0f);
        mrow[a] = 0.0f;
    }
    __syncthreads();

    // Pass 2: extract top-13 by iterative argmax (stable: lower index wins ties).
    for (int k = 0; k < TOPK; k++) {
        float bv = -1.0f;
        int   bi = NA;
        for (int a = tid; a < NA; a += NTHR) {
            float v = s_align[a];
            if (v > bv) { bv = v; bi = a; }   // strided ascending a -> first max kept
        }
        s_redv[tid] = bv;
        s_redi[tid] = bi;
        __syncthreads();
        #pragma unroll
        for (int s = NTHR / 2; s > 0; s >>= 1) {
            if (tid < s) {
                float ov2 = s_redv[tid + s];
                int   oi2 = s_redi[tid + s];
                if (ov2 > s_redv[tid] || (ov2 == s_redv[tid] && oi2 < s_redi[tid])) {
                    s_redv[tid] = ov2;
                    s_redi[tid] = oi2;
                }
            }
            __syncthreads();
        }
        if (tid == 0) {
            s_topv[k] = s_redv[0];
            s_topi[k] = s_redi[0];
            s_align[s_redi[0]] = -2.0f;   // remove; real values are >= 0
        }
        __syncthreads();
    }

    // Recompute IoU at the 13 winners (pos_overlaps needs raw overlaps).
    if (tid < TOPK) {
        int a = s_topi[tid];
        float bx1 = px1[a], by1 = py1[a], bx2 = px2[a], by2 = py2[a];
        float iw = fmaxf(fminf(gx2, bx2) - fmaxf(gx1, bx1), 0.f);
        float ih = fmaxf(fminf(gy2, by2) - fmaxf(gy1, by1), 0.f);
        float ov = iw * ih;
        float a2 = fmaxf(bx2 - bx1, 0.f) * fmaxf(by2 - by1, 0.f);
        s_iou[tid] = ov / (area1 + a2 - ov + EPSF);
    }
    __syncthreads();

    if (tid == 0) {
        float po = 0.f;
        #pragma unroll
        for (int k = 0; k < TOPK; k++) po = fmaxf(po, s_iou[k]);
        // ratio = pos_overlaps / (pos_align_metrics + EPS); pos_align = top1.
        s_ratio = po / (s_topv[0] + EPSF);
    }
    __syncthreads();

    const bool valid = (s_topv[0] > EPSF);
    if (valid && tid < TOPK) {
        int a = s_topi[tid];
        mrow[a] = 1.0f;
        float contrib = s_topv[tid] * s_ratio;   // align * pos_overlaps/(pos_align+eps)
        atomicMax(&d_norm_bits[a], __float_as_uint(contrib));
    }
    // invalid row: mask stays all-zero (cnt>1 collapse in the reference), norm gets no contribution.
}

// target_scores[a, j] = float(gt_labels[j]) * norm[a], shape (NA, BS) row-major.
__global__ __launch_bounds__(NTHR) void taa_target(
    const int* __restrict__ gt_labels,
    float*     __restrict__ target_out)
{
    __shared__ float s_lab[BS];
    if (threadIdx.x < BS) s_lab[threadIdx.x] = (float)gt_labels[threadIdx.x];
    __syncthreads();

    int idx = blockIdx.x * blockDim.x + threadIdx.x;
    if (idx < NA * BS) {
        int a = idx >> 6;          // / BS (64)
        int j = idx & (BS - 1);    // % BS
        target_out[idx] = s_lab[j] * __uint_as_float(d_norm_bits[a]);
    }
}

extern "C" void kernel_launch(void* const* d_in, const int* in_sizes, int n_in,
                              void* d_out, int out_size) {
    const float* pd_scores = (const float*)d_in[0];
    const float* pd_bboxes = (const float*)d_in[1];
    const int*   gt_labels = (const int*)d_in[2];
    const float* gt_bboxes = (const float*)d_in[3];

    float* target = (float*)d_out;                       // (NA, BS) = 537600
    float* mask   = (float*)d_out + (size_t)NA * BS;     // (BS, NA) = 537600

    taa_zero_norm<<<(NA + NTHR - 1) / NTHR, NTHR>>>();
    taa_assign<<<BS, NTHR>>>(pd_scores, pd_bboxes, gt_labels, gt_bboxes, mask);
    taa_target<<<((size_t)NA * BS + NTHR - 1) / NTHR, NTHR>>>(gt_labels, target);
}

// round 6
// speedup vs baseline: 1.9026x; 1.9026x over previous
#include <cuda_runtime.h>

#define BS    64
#define NC    80
#define NA    8400
#define TOPK  13
#define EPSF  1e-9f

#define ATHR  1024
#define ELEM  9            // ceil(NA / ATHR)

// norm_align_metric scratch (float bits). Zero at module load; every call
// leaves it zeroed (taa_target resets its own range after reading).
__device__ unsigned int d_norm_bits[NA];

// One block per batch row. Candidates live in registers as packed u64:
//   (float_bits(align) << 32) | (0xFFFFFFFF - anchor)
// u64 max == (higher align, then lower anchor index)  [align >= 0 always].
// Sentinel 0 (consumed / out-of-range) loses to every real candidate.
__global__ __launch_bounds__(ATHR, 1) void taa_assign(
    const float* __restrict__ pd_scores,   // (BS, NC, NA)
    const float* __restrict__ pd_bboxes,   // (BS, 4, NA)
    const int*   __restrict__ gt_labels,   // (BS,)
    const float* __restrict__ gt_bboxes,   // (BS, 4)
    float*       __restrict__ mask_out)    // (BS, NA)
{
    __shared__ unsigned long long s_part[ATHR / 32];
    __shared__ unsigned long long s_win;
    __shared__ float s_topv[TOPK];
    __shared__ int   s_topi[TOPK];
    __shared__ float s_iou[TOPK];
    __shared__ float s_ratio;

    const int b    = blockIdx.x;
    const int tid  = threadIdx.x;
    const int lane = tid & 31;
    const int wid  = tid >> 5;

    const float gx1 = gt_bboxes[b * 4 + 0];
    const float gy1 = gt_bboxes[b * 4 + 1];
    const float gx2 = gt_bboxes[b * 4 + 2];
    const float gy2 = gt_bboxes[b * 4 + 3];
    const float area1 = fmaxf(gx2 - gx1, 0.f) * fmaxf(gy2 - gy1, 0.f);
    const int   label = gt_labels[b];

    const float* __restrict__ px1 = pd_bboxes + ((long)b * 4 + 0) * NA;
    const float* __restrict__ py1 = pd_bboxes + ((long)b * 4 + 1) * NA;
    const float* __restrict__ px2 = pd_bboxes + ((long)b * 4 + 2) * NA;
    const float* __restrict__ py2 = pd_bboxes + ((long)b * 4 + 3) * NA;
    const float* __restrict__ sc  = pd_scores + ((long)b * NC + label) * NA;
    float* __restrict__ mrow = mask_out + (long)b * NA;

    // Pass 1: align metric -> packed register candidates; zero mask row.
    unsigned long long p[ELEM];
    #pragma unroll
    for (int i = 0; i < ELEM; i++) {
        int a = i * ATHR + tid;
        if (a < NA) {
            float bx1 = px1[a], by1 = py1[a], bx2 = px2[a], by2 = py2[a];
            float iw = fmaxf(fminf(gx2, bx2) - fmaxf(gx1, bx1), 0.f);
            float ih = fmaxf(fminf(gy2, by2) - fmaxf(gy1, by1), 0.f);
            float ov = iw * ih;
            float a2 = fmaxf(bx2 - bx1, 0.f) * fmaxf(by2 - by1, 0.f);
            float iou = ov / (area1 + a2 - ov + EPSF);
            float iou2 = iou * iou;
            float align = sc[a] * (iou2 * iou2 * iou2);
            p[i] = ((unsigned long long)__float_as_uint(align) << 32)
                 | (unsigned long long)(0xFFFFFFFFu - (unsigned)a);
            mrow[a] = 0.0f;
        } else {
            p[i] = 0ull;
        }
    }

    // 13 rounds of block-wide u64-max over register candidates.
    for (int k = 0; k < TOPK; k++) {
        unsigned long long m = 0ull;
        #pragma unroll
        for (int i = 0; i < ELEM; i++) m = (p[i] > m) ? p[i] : m;

        #pragma unroll
        for (int o = 16; o > 0; o >>= 1) {
            unsigned long long t = __shfl_down_sync(0xFFFFFFFFu, m, o);
            if (t > m) m = t;
        }
        if (lane == 0) s_part[wid] = m;
        __syncthreads();
        if (wid == 0) {
            m = s_part[lane];
            #pragma unroll
            for (int o = 16; o > 0; o >>= 1) {
                unsigned long long t = __shfl_down_sync(0xFFFFFFFFu, m, o);
                if (t > m) m = t;
            }
            if (lane == 0) s_win = m;
        }
        __syncthreads();

        unsigned long long win = s_win;
        if (tid == 0) {
            s_topv[k] = __uint_as_float((unsigned)(win >> 32));
            s_topi[k] = (int)(0xFFFFFFFFu - (unsigned)(win & 0xFFFFFFFFull));
        }
        // Consume the winner (u64 payload unique per anchor).
        #pragma unroll
        for (int i = 0; i < ELEM; i++) if (p[i] == win) p[i] = 0ull;
        __syncthreads();
    }

    // Recompute raw IoU at the 13 winners (pos_overlaps).
    if (tid < TOPK) {
        int a = s_topi[tid];
        float bx1 = px1[a], by1 = py1[a], bx2 = px2[a], by2 = py2[a];
        float iw = fmaxf(fminf(gx2, bx2) - fmaxf(gx1, bx1), 0.f);
        float ih = fmaxf(fminf(gy2, by2) - fmaxf(gy1, by1), 0.f);
        float ov = iw * ih;
        float a2 = fmaxf(bx2 - bx1, 0.f) * fmaxf(by2 - by1, 0.f);
        s_iou[tid] = ov / (area1 + a2 - ov + EPSF);
    }
    __syncthreads();

    if (tid == 0) {
        float po = 0.f;
        #pragma unroll
        for (int k = 0; k < TOPK; k++) po = fmaxf(po, s_iou[k]);
        s_ratio = po / (s_topv[0] + EPSF);   // pos_overlaps / (pos_align + eps)
    }
    __syncthreads();

    if (s_topv[0] > EPSF && tid < TOPK) {
        int a = s_topi[tid];
        mrow[a] = 1.0f;
        float contrib = s_topv[tid] * s_ratio;
        atomicMax(&d_norm_bits[a], __float_as_uint(contrib));
    }
    // invalid row: mask all-zero (cnt>1 collapse), no norm contribution.
}

// target_scores[a, j] = float(gt_labels[j]) * norm[a], layout (NA, BS).
// Each block owns a contiguous anchor range and resets its d_norm_bits slice
// after use (sole reader => race-free; leaves scratch zeroed for next call).
#define TANCH 40                    // anchors per block: 8400 = 210 * 40
#define TTHR  256

__global__ __launch_bounds__(TTHR) void taa_target(
    const int* __restrict__ gt_labels,
    float*     __restrict__ target_out)
{
    __shared__ float s_norm[TANCH];
    __shared__ float s_lab[BS];

    const int tid = threadIdx.x;
    const int a0  = blockIdx.x * TANCH;

    if (tid < TANCH) s_norm[tid] = __uint_as_float(d_norm_bits[a0 + tid]);
    if (tid >= 64 && tid < 64 + BS) s_lab[tid - 64] = (float)gt_labels[tid - 64];
    __syncthreads();

    float* __restrict__ outp = target_out + (long)a0 * BS;
    #pragma unroll
    for (int j = 0; j < (TANCH * BS) / TTHR; j++) {
        int o = j * TTHR + tid;
        outp[o] = s_lab[o & (BS - 1)] * s_norm[o >> 6];
    }
    __syncthreads();
    if (tid < TANCH) d_norm_bits[a0 + tid] = 0u;
}

extern "C" void kernel_launch(void* const* d_in, const int* in_sizes, int n_in,
                              void* d_out, int out_size) {
    const float* pd_scores = (const float*)d_in[0];
    const float* pd_bboxes = (const float*)d_in[1];
    const int*   gt_labels = (const int*)d_in[2];
    const float* gt_bboxes = (const float*)d_in[3];

    float* target = (float*)d_out;                       // (NA, BS)
    float* mask   = (float*)d_out + (size_t)NA * BS;     // (BS, NA)

    taa_assign<<<BS, ATHR>>>(pd_scores, pd_bboxes, gt_labels, gt_bboxes, mask);
    taa_target<<<NA / TANCH, TTHR>>>(gt_labels, target);
}